// round 17
// baseline (speedup 1.0000x reference)
#include <cuda_runtime.h>
#include <cuda_bf16.h>
#include <stdint.h>

// Problem constants
#define BB 4
#define HH 4
#define BH (BB*HH)          // 16
#define VV 8
#define NN 16384
#define FD 32
#define NC 32768            // 32*32*32
#define NE (VV*NN)          // entries per bh = 131072
#define NE_TOT (BH*NE)      // 2,097,152 total entries
#define KCAP 8              // bucket capacity (measured optimum; do not raise)
#define SPILL_CAP 65536
#define CPB 64              // cells per gather block
#define GTHREADS 512        // gather block size (16 warps x 4 cells = 64)

#define TRANS_BLOCKS 8192                    // BH * NN/32
#define SCAT_BLOCKS  512                     // NE_TOT/4/1024
#define PREP_BLOCKS  (TRANS_BLOCKS + SCAT_BLOCKS)   // 8704 = 512*17
// role: bid % 17 == 0 -> scatter (bids 0,17,...,8687); else transpose

// ---------------------------------------------------------------------------
// Scratch (device globals — start zeroed; self-cleaning invariant: every
// run leaves g_count == 0 and g_spill_cnt == 0 for the next replay)
// ---------------------------------------------------------------------------
__device__ float g_featsT [BH * NN * FD];        // 32 MB [bh][n][f]
__device__ uint2 g_entries[BH * NC * KCAP];      // 32 MB {n, bits(lc)}
__device__ int   g_count  [BH * NC];             // 2 MB (re-zeroed by gather)
__device__ uint4 g_spill  [SPILL_CAP];           // {bh, c, n, bits(lc)}
__device__ int   g_spill_cnt;                    // snapshot+zeroed by gather
__device__ int   g_spill_cnt_copy;               // read by spill

// ---------------------------------------------------------------------------
// 1) prep: INTERLEAVED fused transpose + scatter (co-resident from wave 1).
//    Scatter role (bid%17==0): 1024 thr x 4 entries, batched atomics.
//    Transpose role: one 32x32 tile of feats -> feats_T.
// block 1024
// ---------------------------------------------------------------------------
__global__ void prep_kernel(const float* __restrict__ feats,
                            const float* __restrict__ lc,
                            const int* __restrict__ fidx) {
    __shared__ float tile[32][33];
    const int bid = blockIdx.x;

    if (bid % 17 == 0) {
        // ---- scatter role ----
        const int q  = (bid / 17) * 1024 + threadIdx.x;   // quad idx, 0..524287
        const int bh = q >> 15;                            // / (NE/4)
        const int tq = q & ((NE / 4) - 1);
        const int i0 = tq * 4;                             // entry idx within bh

        const int4   cc = ((const int4*)fidx)[q];
        const float4 ll = ((const float4*)lc)[q];
        const int   cs[4] = {cc.x & (NC - 1), cc.y & (NC - 1),
                             cc.z & (NC - 1), cc.w & (NC - 1)};
        const float ls[4] = {ll.x, ll.y, ll.z, ll.w};

        int pos[4], bhc[4];
#pragma unroll
        for (int k = 0; k < 4; k++) {
            bhc[k] = bh * NC + cs[k];
            pos[k] = atomicAdd(&g_count[bhc[k]], 1);
        }
#pragma unroll
        for (int k = 0; k < 4; k++) {
            const int n = (i0 + k) & (NN - 1);
            if (pos[k] < KCAP) {
                g_entries[(size_t)bhc[k] * KCAP + pos[k]] =
                    make_uint2((unsigned)n, __float_as_uint(ls[k]));
            } else {
                int sp = atomicAdd(&g_spill_cnt, 1);
                if (sp < SPILL_CAP)
                    g_spill[sp] = make_uint4((unsigned)bh, (unsigned)cs[k],
                                             (unsigned)n, __float_as_uint(ls[k]));
            }
        }
    } else {
        // ---- transpose role ----
        const int tbid = bid - bid / 17 - 1;     // 0..8191
        const int bh = tbid >> 9;                // /512
        const int n0 = (tbid & 511) * 32;
        const int tx = threadIdx.x & 31, ty = threadIdx.x >> 5;
        tile[ty][tx] = feats[(bh * FD + ty) * NN + n0 + tx];     // coalesced n
        __syncthreads();
        g_featsT[(bh * NN + n0 + ty) * FD + tx] = tile[tx][ty];  // coalesced f
    }
}

// ---------------------------------------------------------------------------
// 2) gather: block = 64 cells; warp = 4 cells; lane = (cell_sub, f_quad).
//    Entry loads batched to registers; unrolled predicated LDG.128 batch.
//    Self-cleans g_count; block (0,0) snapshots+zeros g_spill_cnt.
// grid (NC/CPB, BH), block 512
// ---------------------------------------------------------------------------
__global__ void gather_kernel(float* __restrict__ out) {
    __shared__ uint2 s_ent[CPB * KCAP];     // 4 KB
    __shared__ int   s_cnt[CPB];
    __shared__ float s_tile[FD][CPB + 1];   // ~8.1 KB

    const int bh = blockIdx.y;
    const int c0 = blockIdx.x * CPB;
    const int t  = threadIdx.x;

    // spill counter snapshot (completes before spill_kernel launches)
    if (blockIdx.x == 0 && blockIdx.y == 0 && t == 0) {
        g_spill_cnt_copy = g_spill_cnt;
        g_spill_cnt = 0;
    }

    // Phase 1: one-round coalesced staging + count read/clear
    s_ent[t] = g_entries[(size_t)(bh * NC + c0) * KCAP + t];
    if (t < CPB) {
        const int gi = bh * NC + c0 + t;
        s_cnt[t] = min(g_count[gi], KCAP);
        g_count[gi] = 0;                     // self-clean for next replay
    }
    __syncthreads();

    // Phase 2: warp w -> cells w*4 .. w*4+3
    const int lane = t & 31;
    const int w    = t >> 5;
    const int cs   = lane >> 3;        // cell within warp (0..3)
    const int fq   = lane & 7;         // float4 index (f = fq*4 .. fq*4+3)
    const int cell = w * 4 + cs;

    const int cnt = s_cnt[cell];
    const float4* __restrict__ ft4 =
        (const float4*)g_featsT + (size_t)bh * NN * (FD / 4);
    const uint2* __restrict__ ep = &s_ent[cell * KCAP];

    uint2 e[KCAP];
#pragma unroll
    for (int j = 0; j < KCAP; j++) e[j] = ep[j];

    float4 m4 = make_float4(0.f, 0.f, 0.f, 0.f);
#pragma unroll
    for (int j = 0; j < KCAP; j++) {
        if (j < cnt) {
            const float4 fv = ft4[e[j].x * (FD / 4) + fq];   // LDG.128
            const float  l  = __uint_as_float(e[j].y);
            m4.x = fmaxf(m4.x, fv.x * l);
            m4.y = fmaxf(m4.y, fv.y * l);
            m4.z = fmaxf(m4.z, fv.z * l);
            m4.w = fmaxf(m4.w, fv.w * l);
        }
    }

    s_tile[fq * 4 + 0][cell] = m4.x;    // stride 65: conflict-free
    s_tile[fq * 4 + 1][cell] = m4.y;
    s_tile[fq * 4 + 2][cell] = m4.z;
    s_tile[fq * 4 + 3][cell] = m4.w;
    __syncthreads();

    // Phase 3: one round of float4 stores (512 x 16B = whole tile)
    {
        const int f   = t >> 4;              // 0..31
        const int cl0 = (t & 15) * 4;        // 0..60
        const float4 v = make_float4(s_tile[f][cl0 + 0], s_tile[f][cl0 + 1],
                                     s_tile[f][cl0 + 2], s_tile[f][cl0 + 3]);
        *(float4*)(out + ((size_t)bh * FD + f) * NC + c0 + cl0) = v;
    }
}

// ---------------------------------------------------------------------------
// 3) spill: entry-level parallel. thread = (entry, f-quad): 8 threads per
//    entry, each 1 float4 feats load + 4 predicated spread atomicMax.
// ---------------------------------------------------------------------------
__global__ void spill_kernel(float* __restrict__ out) {
    const int tid = blockIdx.x * blockDim.x + threadIdx.x;
    const int fq  = tid & 7;            // float4 quarter (f = fq*4..fq*4+3)
    const int nt  = (gridDim.x * blockDim.x) >> 3;
    const int cnt = min(g_spill_cnt_copy, SPILL_CAP);
    for (int s = tid >> 3; s < cnt; s += nt) {
        const uint4 e = g_spill[s];     // 8 threads share -> broadcast
        const int bh = (int)e.x, c = (int)e.y, n = (int)e.z;
        const float l = __uint_as_float(e.w);
        const float4 fv = ((const float4*)g_featsT)
                              [((size_t)bh * NN + n) * (FD / 4) + fq];
        int* const ob = (int*)out + ((size_t)bh * FD + fq * 4) * NC + c;
        const float v0 = fv.x * l, v1 = fv.y * l, v2 = fv.z * l, v3 = fv.w * l;
        if (v0 > 0.f) atomicMax(ob + 0 * NC, __float_as_int(v0));
        if (v1 > 0.f) atomicMax(ob + 1 * NC, __float_as_int(v1));
        if (v2 > 0.f) atomicMax(ob + 2 * NC, __float_as_int(v2));
        if (v3 > 0.f) atomicMax(ob + 3 * NC, __float_as_int(v3));
    }
}

// ---------------------------------------------------------------------------
// kernel_launch
//   d_in[0] local_coordinate  float32 [B,H,V,N]
//   d_in[1] flattened_index   int32   [B,H,V,N]
//   d_in[2] features          float32 [B,128,N]
//   d_out   float32 [B,128,32,32,32]
// ---------------------------------------------------------------------------
extern "C" void kernel_launch(void* const* d_in, const int* in_sizes, int n_in,
                              void* d_out, int out_size) {
    const float* lc    = (const float*)d_in[0];
    const int*   fidx  = (const int*)d_in[1];
    const float* feats = (const float*)d_in[2];
    float*       out   = (float*)d_out;

    // 1) interleaved fused transpose + scatter
    prep_kernel<<<PREP_BLOCKS, 1024>>>(feats, lc, fidx);

    // 2) gather -> out (writes every cell; self-cleans counters)
    {
        dim3 grid(NC / CPB, BH);
        gather_kernel<<<grid, GTHREADS>>>(out);
    }

    // 3) spills (entry-level parallel)
    spill_kernel<<<592, 256>>>(out);
}